// round 5
// baseline (speedup 1.0000x reference)
#include <cuda_runtime.h>

#define NND 20000
#define NE  640000
#define NG  256
#define HD  128
#define ED  64
#define GD  64
#define HID 128

#define PE  68
#define PX  132
#define PU  68
#define PA  36
#define PB  136
#define PB3 72
#define LDR 132

// ---------------- scratch ----------------
__device__ float d_gmap[NG * HID];
__device__ float d_nsum[NND];
__device__ float d_maggr[(size_t)NND * HID];
__device__ float d_gsumh[NG];
__device__ float d_gsume[NG];
__device__ float d_haggr[NG * HID];
__device__ float d_eaggr[NG * ED];

// ---------------- helpers ----------------
__device__ __forceinline__ void mma8(float* c, const unsigned* a, const unsigned* b) {
    asm volatile(
        "mma.sync.aligned.m16n8k8.row.col.f32.tf32.tf32.f32 "
        "{%0,%1,%2,%3}, {%4,%5,%6,%7}, {%8,%9}, {%0,%1,%2,%3};"
        : "+f"(c[0]), "+f"(c[1]), "+f"(c[2]), "+f"(c[3])
        : "r"(a[0]), "r"(a[1]), "r"(a[2]), "r"(a[3]), "r"(b[0]), "r"(b[1]));
}
__device__ __forceinline__ void cp16(void* s, const void* g) {
    unsigned sa = (unsigned)__cvta_generic_to_shared(s);
    asm volatile("cp.async.cg.shared.global [%0], [%1], 16;" :: "r"(sa), "l"(g));
}
#define CP_COMMIT asm volatile("cp.async.commit_group;")
#define CP_WAIT0  asm volatile("cp.async.wait_group 0;")

__device__ __forceinline__ void red4(float* g, float4 v) {
    asm volatile("red.global.add.v4.f32 [%0], {%1,%2,%3,%4};"
                 :: "l"(g), "f"(v.x), "f"(v.y), "f"(v.z), "f"(v.w) : "memory");
}

// one k8 (8-wide) MMA step: MT 16-row tiles x NT 8-col tiles
template <int MT, int NT>
__device__ __forceinline__ void mma_step(float (*c)[NT][4],
                                         const float* At, int padA, int coff,
                                         const float* Bt, int padB, int cbase,
                                         int rbase, int g, int kq, int k8) {
    unsigned a[MT][4];
#pragma unroll
    for (int mt = 0; mt < MT; mt++) {
        const float* p = At + (rbase + mt * 16 + g) * padA + coff + k8 * 8 + kq;
        a[mt][0] = __float_as_uint(p[0]);
        a[mt][1] = __float_as_uint(p[8 * padA]);
        a[mt][2] = __float_as_uint(p[4]);
        a[mt][3] = __float_as_uint(p[8 * padA + 4]);
    }
    unsigned b[NT][2];
#pragma unroll
    for (int nt = 0; nt < NT; nt++) {
        const float* p = Bt + (k8 * 8 + kq) * padB + cbase + nt * 8 + g;
        b[nt][0] = __float_as_uint(p[0]);
        b[nt][1] = __float_as_uint(p[4 * padB]);
    }
#pragma unroll
    for (int mt = 0; mt < MT; mt++)
#pragma unroll
        for (int nt = 0; nt < NT; nt++) mma8(c[mt][nt], a[mt], b[nt]);
}

// ---------------- init ----------------
__global__ void k_init() {
    int i  = blockIdx.x * blockDim.x + threadIdx.x;
    int st = gridDim.x * blockDim.x;
    for (int j = i; j < NND; j += st) d_nsum[j] = 0.f;
    for (int j = i; j < NND * HID; j += st) d_maggr[j] = 0.f;
    for (int j = i; j < NG; j += st) { d_gsumh[j] = 0.f; d_gsume[j] = 0.f; }
    for (int j = i; j < NG * HID; j += st) d_haggr[j] = 0.f;
    for (int j = i; j < NG * ED;  j += st) d_eaggr[j] = 0.f;
}

// ---------------- g_map ----------------
__global__ void k_gmap(const float* __restrict__ g, const float* __restrict__ Wmap,
                       const float* __restrict__ bmap) {
    int r = blockIdx.x, c = threadIdx.x;
    __shared__ float sg[GD];
    if (c < GD) sg[c] = g[r * GD + c];
    __syncthreads();
    float s = bmap[c];
#pragma unroll
    for (int k = 0; k < GD; k++) s += sg[k] * Wmap[k * HID + c];
    d_gmap[r * HID + c] = s;
}

// ---------------- node->graph ----------------
__global__ void k_hagg(const float* __restrict__ h, const int* __restrict__ batch,
                       const float* __restrict__ Wha, const float* __restrict__ bhaP) {
    int w = (blockIdx.x * blockDim.x + threadIdx.x) >> 5;
    int lane = threadIdx.x & 31;
    if (w >= NND) return;
    float4 hv = *(const float4*)(h + (size_t)w * HD + lane * 4);
    float4 wv = *(const float4*)(Wha + lane * 4);
    float s = hv.x * wv.x + hv.y * wv.y + hv.z * wv.z + hv.w * wv.w;
#pragma unroll
    for (int off = 16; off; off >>= 1) s += __shfl_xor_sync(0xffffffffu, s, off);
    int b = batch[w];
    float ew = expf(s + bhaP[0]);
    if (lane == 0) atomicAdd(&d_gsumh[b], ew);
    red4(d_haggr + b * HD + lane * 4,
         make_float4(hv.x * ew, hv.y * ew, hv.z * ew, hv.w * ew));
}

// ---------------- fused edge kernel: 8 warps = 2x2 grid x 2 k-halves ----------
__global__ __launch_bounds__(256, 1) void k_edge(
    const float* __restrict__ h, const float* __restrict__ e,
    const int* __restrict__ eidx, const int* __restrict__ batch,
    const float* __restrict__ Wm1, const float* __restrict__ bm1,
    const float* __restrict__ Wm2, const float* __restrict__ bm2,
    const float* __restrict__ Wma, const float* __restrict__ bmaP,
    const float* __restrict__ We1, const float* __restrict__ be1,
    const float* __restrict__ We2, const float* __restrict__ be2,
    const float* __restrict__ Wea, const float* __restrict__ beaP,
    float* __restrict__ eout)
{
    extern __shared__ float smp[];
    float* sE    = smp;                       // 128*PE
    float* sX    = sE + 128 * PE;             // 128*PX
    float* sA    = sX + 128 * PX;             // 2*128*PA (GEMM1 h tiles)
    float* sU    = sA;                        // alias (sA dead after GEMM1)
    float* sB    = sA + 2 * 128 * PA;         // 2*32*PB
    float* sWma  = sB + 2 * 32 * PB;
    float* sWea  = sWma + 128;
    float* sMatt = sWea + 64;
    float* sWeat = sMatt + 128;
    float* sBm1  = sWeat + 128;
    float* sBm2  = sBm1 + 128;
    float* sBe1  = sBm2 + 128;
    float* sBe2  = sBe1 + 64;
    int* sDst = (int*)(sBe2 + 64);
    int* sSrc = sDst + 128;
    int* sBat = sSrc + 128;

    const int tid  = threadIdx.x;
    const int lane = tid & 31;
    const int wid  = tid >> 5;
    const int ry   = wid >> 2;        // 0..1 : rows [ry*64, ry*64+64)
    const int cx   = (wid >> 1) & 1;  // 0..1 : col group
    const int kh   = wid & 1;         // 0..1 : k8 half {kh*2, kh*2+1}
    const int g    = lane >> 2;
    const int kq   = lane & 3;
    const int e0   = blockIdx.x * 128;

    if (tid < 128) {
        int d = eidx[NE + e0 + tid];
        sDst[tid] = d;
        sSrc[tid] = eidx[e0 + tid];
        sBat[tid] = batch[d];
        sWma[tid] = Wma[tid];
        sMatt[tid] = bmaP[0];
        sBm1[tid] = bm1[tid];
        sBm2[tid] = bm2[tid];
    }
    if (tid < 64) { sWea[tid] = Wea[tid]; sBe1[tid] = be1[tid]; sBe2[tid] = be2[tid]; }
    __syncthreads();

#pragma unroll
    for (int i = 0; i < 8; i++) {
        int c = tid + i * 256;
        int row = c >> 4, q = c & 15;
        cp16(sE + row * PE + q * 4, e + (size_t)(e0 + row) * ED + q * 4);
    }
#pragma unroll
    for (int i = 0; i < 4; i++) {
        int c = tid + i * 256;
        int row = c >> 3, q = c & 7;
        cp16(sA + row * PA + q * 4, h + (size_t)sDst[row] * HD + q * 4);
    }
#pragma unroll
    for (int i = 0; i < 4; i++) {
        int c = tid + i * 256;
        int row = c >> 5, q = c & 31;
        cp16(sB + row * PB + q * 4, Wm1 + (size_t)row * HID + q * 4);
    }
    CP_COMMIT;

    // ================= GEMM1 =================
    float acc[4][8][4];
#pragma unroll
    for (int mt = 0; mt < 4; mt++)
#pragma unroll
        for (int nt = 0; nt < 8; nt++)
#pragma unroll
            for (int i = 0; i < 4; i++) acc[mt][nt][i] = 0.f;

    for (int t = 0; t < 10; t++) {
        CP_WAIT0;
        __syncthreads();
        if (t < 9) {
            int tn = t + 1;
            if (tn < 8) {
#pragma unroll
                for (int i = 0; i < 4; i++) {
                    int c = tid + i * 256;
                    int row = c >> 3, q = c & 7;
                    const float* src = (tn < 4)
                        ? h + (size_t)sDst[row] * HD + tn * 32 + q * 4
                        : h + (size_t)sSrc[row] * HD + (tn - 4) * 32 + q * 4;
                    cp16(sA + ((tn & 1) * 128 * PA) + row * PA + q * 4, src);
                }
            }
#pragma unroll
            for (int i = 0; i < 4; i++) {
                int c = tid + i * 256;
                int row = c >> 5, q = c & 31;
                cp16(sB + ((tn & 1) * 32 * PB) + row * PB + q * 4,
                     Wm1 + (size_t)(tn * 32 + row) * HID + q * 4);
            }
            CP_COMMIT;
        }
        const float* At; int padA, coff;
        if (t < 8) { At = sA + (t & 1) * 128 * PA; padA = PA; coff = 0; }
        else       { At = sE; padA = PE; coff = (t - 8) * 32; }
        const float* Bt = sB + (t & 1) * 32 * PB;
        mma_step<4, 8>(acc, At, padA, coff, Bt, PB, cx * 64, ry * 64, g, kq, kh * 2);
        mma_step<4, 8>(acc, At, padA, coff, Bt, PB, cx * 64, ry * 64, g, kq, kh * 2 + 1);
    }

    // epilogue 1: merge k-halves (kh0 writes, kh1 adds+relu+bias)
#pragma unroll
    for (int mt = 0; mt < 4; mt++) {
        int r0 = ry * 64 + mt * 16 + g;
        if (kh == 0) {
#pragma unroll
            for (int nt = 0; nt < 8; nt++) {
                int col = cx * 64 + nt * 8 + kq * 2;
                *(float2*)&sX[r0 * PX + col]       = make_float2(acc[mt][nt][0], acc[mt][nt][1]);
                *(float2*)&sX[(r0 + 8) * PX + col] = make_float2(acc[mt][nt][2], acc[mt][nt][3]);
            }
        }
    }
    __syncthreads();
#pragma unroll
    for (int mt = 0; mt < 4; mt++) {
        int r0 = ry * 64 + mt * 16 + g;
        if (kh == 1) {
#pragma unroll
            for (int nt = 0; nt < 8; nt++) {
                int col = cx * 64 + nt * 8 + kq * 2;
                float b0 = sBm1[col], b1 = sBm1[col + 1];
                float2 p0 = *(const float2*)&sX[r0 * PX + col];
                float2 p1 = *(const float2*)&sX[(r0 + 8) * PX + col];
                *(float2*)&sX[r0 * PX + col] =
                    make_float2(fmaxf(p0.x + acc[mt][nt][0] + b0, 0.f),
                                fmaxf(p0.y + acc[mt][nt][1] + b1, 0.f));
                *(float2*)&sX[(r0 + 8) * PX + col] =
                    make_float2(fmaxf(p1.x + acc[mt][nt][2] + b0, 0.f),
                                fmaxf(p1.y + acc[mt][nt][3] + b1, 0.f));
            }
        }
    }
    __syncthreads();

#pragma unroll
    for (int i = 0; i < 4; i++) {
        int c = tid + i * 256;
        int row = c >> 5, q = c & 31;
        cp16(sB + row * PB + q * 4, Wm2 + (size_t)row * HID + q * 4);
    }
    CP_COMMIT;

    // ================= GEMM2 =================
#pragma unroll
    for (int mt = 0; mt < 4; mt++)
#pragma unroll
        for (int nt = 0; nt < 8; nt++)
#pragma unroll
            for (int i = 0; i < 4; i++) acc[mt][nt][i] = 0.f;

    for (int t = 0; t < 4; t++) {
        CP_WAIT0;
        __syncthreads();
        if (t < 3) {
            int tn = t + 1;
#pragma unroll
            for (int i = 0; i < 4; i++) {
                int c = tid + i * 256;
                int row = c >> 5, q = c & 31;
                cp16(sB + ((tn & 1) * 32 * PB) + row * PB + q * 4,
                     Wm2 + (size_t)(tn * 32 + row) * HID + q * 4);
            }
            CP_COMMIT;
        }
        const float* Bt = sB + (t & 1) * 32 * PB;
        mma_step<4, 8>(acc, sX, PX, t * 32, Bt, PB, cx * 64, ry * 64, g, kq, kh * 2);
        mma_step<4, 8>(acc, sX, PX, t * 32, Bt, PB, cx * 64, ry * 64, g, kq, kh * 2 + 1);
    }
    __syncthreads();

    // epilogue 2: merge halves -> m in sX; m_att partials (kh1 computes final)
#pragma unroll
    for (int mt = 0; mt < 4; mt++) {
        int r0 = ry * 64 + mt * 16 + g;
        if (kh == 0) {
#pragma unroll
            for (int nt = 0; nt < 8; nt++) {
                int col = cx * 64 + nt * 8 + kq * 2;
                *(float2*)&sX[r0 * PX + col]       = make_float2(acc[mt][nt][0], acc[mt][nt][1]);
                *(float2*)&sX[(r0 + 8) * PX + col] = make_float2(acc[mt][nt][2], acc[mt][nt][3]);
            }
        }
    }
    __syncthreads();
    if (kh == 1) {
        float pa[8];
#pragma unroll
        for (int i = 0; i < 8; i++) pa[i] = 0.f;
#pragma unroll
        for (int mt = 0; mt < 4; mt++) {
            int r0 = ry * 64 + mt * 16 + g;
#pragma unroll
            for (int nt = 0; nt < 8; nt++) {
                int col = cx * 64 + nt * 8 + kq * 2;
                float b0 = sBm2[col], b1 = sBm2[col + 1];
                float2 p0 = *(const float2*)&sX[r0 * PX + col];
                float2 p1 = *(const float2*)&sX[(r0 + 8) * PX + col];
                float v0 = fmaxf(p0.x + acc[mt][nt][0] + b0, 0.f);
                float v1 = fmaxf(p0.y + acc[mt][nt][1] + b1, 0.f);
                float v2 = fmaxf(p1.x + acc[mt][nt][2] + b0, 0.f);
                float v3 = fmaxf(p1.y + acc[mt][nt][3] + b1, 0.f);
                *(float2*)&sX[r0 * PX + col]       = make_float2(v0, v1);
                *(float2*)&sX[(r0 + 8) * PX + col] = make_float2(v2, v3);
                float w0 = sWma[col], w1 = sWma[col + 1];
                pa[mt * 2 + 0] += v0 * w0 + v1 * w1;
                pa[mt * 2 + 1] += v2 * w0 + v3 * w1;
            }
        }
#pragma unroll
        for (int off = 1; off <= 2; off <<= 1)
#pragma unroll
            for (int i = 0; i < 8; i++) pa[i] += __shfl_xor_sync(0xffffffffu, pa[i], off);
        if (kq == 0) {
#pragma unroll
            for (int mt = 0; mt < 4; mt++) {
                atomicAdd(&sMatt[ry * 64 + mt * 16 + g],     pa[mt * 2 + 0]);
                atomicAdd(&sMatt[ry * 64 + mt * 16 + g + 8], pa[mt * 2 + 1]);
            }
        }
    }
    __syncthreads();

    if (tid < 128) {
        float w = expf(sMatt[tid]);
        sMatt[tid] = w;
        atomicAdd(&d_nsum[sDst[tid]], w);
        float s = beaP[0];
        const float* ep = sE + tid * PE;
#pragma unroll 8
        for (int k = 0; k < ED; k++) s += ep[k] * sWea[k];
        float we = expf(s);
        sWeat[tid] = we;
        atomicAdd(&d_gsume[sBat[tid]], we);
    }
#pragma unroll
    for (int i = 0; i < 2; i++) {
        int c = tid + i * 256;
        int row = c >> 4, q = c & 15;
        cp16(sB + row * PB3 + q * 4, We1 + (size_t)row * ED + q * 4);
    }
    CP_COMMIT;
    __syncthreads();

    // combined pass: weighted v4-REDs + Y = m + gmap in place
    {
        int row = tid >> 1, half = tid & 1;
        float wgt = sMatt[row];
        float wee = sWeat[row];
        int dnode = sDst[row];
        int b = sBat[row];
        const float* gm = d_gmap + (size_t)b * HID + half * 64;
        float* mrow = sX + row * PX + half * 64;
        float* mg = d_maggr + (size_t)dnode * HID + half * 64;
#pragma unroll
        for (int j = 0; j < 16; j++) {
            float4 mv = *(const float4*)(mrow + j * 4);
            red4(mg + j * 4, make_float4(mv.x * wgt, mv.y * wgt, mv.z * wgt, mv.w * wgt));
            float4 gv = *(const float4*)(gm + j * 4);
            *(float4*)(mrow + j * 4) =
                make_float4(mv.x + gv.x, mv.y + gv.y, mv.z + gv.z, mv.w + gv.w);
        }
        const float* ep2 = sE + row * PE + half * 32;
        float* ea = d_eaggr + (size_t)b * ED + half * 32;
#pragma unroll
        for (int j = 0; j < 8; j++) {
            float4 ev = *(const float4*)(ep2 + j * 4);
            red4(ea + j * 4, make_float4(ev.x * wee, ev.y * wee, ev.z * wee, ev.w * wee));
        }
    }

    // ================= GEMM3 =================
    float a3[4][4][4];
#pragma unroll
    for (int mt = 0; mt < 4; mt++)
#pragma unroll
        for (int nt = 0; nt < 4; nt++)
#pragma unroll
            for (int i = 0; i < 4; i++) a3[mt][nt][i] = 0.f;

    for (int t = 0; t < 6; t++) {
        CP_WAIT0;
        __syncthreads();
        if (t < 5) {
            int tn = t + 1;
#pragma unroll
            for (int i = 0; i < 2; i++) {
                int c = tid + i * 256;
                int row = c >> 4, q = c & 15;
                cp16(sB + ((tn & 1) * 32 * PB3) + row * PB3 + q * 4,
                     We1 + (size_t)(tn * 32 + row) * ED + q * 4);
            }
            CP_COMMIT;
        }
        const float* At; int padA, coff;
        if (t < 2) { At = sE; padA = PE; coff = t * 32; }
        else       { At = sX; padA = PX; coff = (t - 2) * 32; }
        const float* Bt = sB + (t & 1) * 32 * PB3;
        mma_step<4, 4>(a3, At, padA, coff, Bt, PB3, cx * 32, ry * 64, g, kq, kh * 2);
        mma_step<4, 4>(a3, At, padA, coff, Bt, PB3, cx * 32, ry * 64, g, kq, kh * 2 + 1);
    }

    // epilogue 3: merge halves -> U = relu(sum+be1) in sU
#pragma unroll
    for (int mt = 0; mt < 4; mt++) {
        int r0 = ry * 64 + mt * 16 + g;
        if (kh == 0) {
#pragma unroll
            for (int nt = 0; nt < 4; nt++) {
                int col = cx * 32 + nt * 8 + kq * 2;
                *(float2*)&sU[r0 * PU + col]       = make_float2(a3[mt][nt][0], a3[mt][nt][1]);
                *(float2*)&sU[(r0 + 8) * PU + col] = make_float2(a3[mt][nt][2], a3[mt][nt][3]);
            }
        }
    }
    __syncthreads();
#pragma unroll
    for (int mt = 0; mt < 4; mt++) {
        int r0 = ry * 64 + mt * 16 + g;
        if (kh == 1) {
#pragma unroll
            for (int nt = 0; nt < 4; nt++) {
                int col = cx * 32 + nt * 8 + kq * 2;
                float b0 = sBe1[col], b1 = sBe1[col + 1];
                float2 p0 = *(const float2*)&sU[r0 * PU + col];
                float2 p1 = *(const float2*)&sU[(r0 + 8) * PU + col];
                *(float2*)&sU[r0 * PU + col] =
                    make_float2(fmaxf(p0.x + a3[mt][nt][0] + b0, 0.f),
                                fmaxf(p0.y + a3[mt][nt][1] + b1, 0.f));
                *(float2*)&sU[(r0 + 8) * PU + col] =
                    make_float2(fmaxf(p1.x + a3[mt][nt][2] + b0, 0.f),
                                fmaxf(p1.y + a3[mt][nt][3] + b1, 0.f));
            }
        }
    }
#pragma unroll
    for (int i = 0; i < 2; i++) {
        int c = tid + i * 256;
        int row = c >> 4, q = c & 15;
        cp16(sB + row * PB3 + q * 4, We2 + (size_t)row * ED + q * 4);
    }
    CP_COMMIT;

    // ================= GEMM4 =================
#pragma unroll
    for (int mt = 0; mt < 4; mt++)
#pragma unroll
        for (int nt = 0; nt < 4; nt++)
#pragma unroll
            for (int i = 0; i < 4; i++) a3[mt][nt][i] = 0.f;

    for (int t = 0; t < 2; t++) {
        CP_WAIT0;
        __syncthreads();
        if (t < 1) {
#pragma unroll
            for (int i = 0; i < 2; i++) {
                int c = tid + i * 256;
                int row = c >> 4, q = c & 15;
                cp16(sB + (32 * PB3) + row * PB3 + q * 4,
                     We2 + (size_t)(32 + row) * ED + q * 4);
            }
            CP_COMMIT;
        }
        const float* Bt = sB + (t & 1) * 32 * PB3;
        mma_step<4, 4>(a3, sU, PU, t * 32, Bt, PB3, cx * 32, ry * 64, g, kq, kh * 2);
        mma_step<4, 4>(a3, sU, PU, t * 32, Bt, PB3, cx * 32, ry * 64, g, kq, kh * 2 + 1);
    }

    // final: merge k-halves through sX (dead), then e_out = relu(e + sum + be2)
    __syncthreads();
#pragma unroll
    for (int mt = 0; mt < 4; mt++) {
        int r0 = ry * 64 + mt * 16 + g;
        if (kh == 0) {
#pragma unroll
            for (int nt = 0; nt < 4; nt++) {
                int col = cx * 32 + nt * 8 + kq * 2;
                *(float2*)&sX[r0 * PX + col]       = make_float2(a3[mt][nt][0], a3[mt][nt][1]);
                *(float2*)&sX[(r0 + 8) * PX + col] = make_float2(a3[mt][nt][2], a3[mt][nt][3]);
            }
        }
    }
    __syncthreads();
#pragma unroll
    for (int mt = 0; mt < 4; mt++) {
        int r0 = ry * 64 + mt * 16 + g, r1 = r0 + 8;
        if (kh == 1) {
#pragma unroll
            for (int nt = 0; nt < 4; nt++) {
                int col = cx * 32 + nt * 8 + kq * 2;
                float b0 = sBe2[col], b1 = sBe2[col + 1];
                float2 p0 = *(const float2*)&sX[r0 * PX + col];
                float2 p1 = *(const float2*)&sX[r1 * PX + col];
                float2 e0v = *(const float2*)&sE[r0 * PE + col];
                float2 e1v = *(const float2*)&sE[r1 * PE + col];
                *(float2*)&eout[(size_t)(e0 + r0) * ED + col] =
                    make_float2(fmaxf(e0v.x + p0.x + a3[mt][nt][0] + b0, 0.f),
                                fmaxf(e0v.y + p0.y + a3[mt][nt][1] + b1, 0.f));
                *(float2*)&eout[(size_t)(e0 + r1) * ED + col] =
                    make_float2(fmaxf(e1v.x + p1.x + a3[mt][nt][2] + b0, 0.f),
                                fmaxf(e1v.y + p1.y + a3[mt][nt][3] + b1, 0.f));
            }
        }
    }
}

// ---------------- node update GEMM (fp32) ----------------
__global__ __launch_bounds__(256, 1) void k_node(
    const float* __restrict__ h, const int* __restrict__ batch,
    const float* __restrict__ Wh1, const float* __restrict__ bh1,
    const float* __restrict__ Wh2, const float* __restrict__ bh2,
    float* __restrict__ hout)
{
    extern __shared__ float smp[];
    float* sZ   = smp;
    float* sX1  = sZ + 128 * LDR;
    float* sAs  = sX1 + 128 * LDR;
    float* sBs  = sAs + 8 * LDR;
    float* sInv = sBs + 8 * 128;
    int* sN  = (int*)(sInv + 128);
    int* sBt = sN + 128;

    int tid = threadIdx.x, tx = tid & 15, ty = tid >> 4;
    int n0 = blockIdx.x * 128;
    if (tid < 128) {
        int n = n0 + tid;
        if (n >= NND) n = NND - 1;
        sN[tid] = n;
        sBt[tid] = batch[n];
        sInv[tid] = 1.f / (d_nsum[n] + 1e-16f);
    }
    __syncthreads();
    for (int i = tid; i < 128 * 32; i += 256) {
        int row = i >> 5, c4 = (i & 31) << 2;
        int n = sN[row];
        float inv = sInv[row];
        const float* gm = d_gmap + (size_t)sBt[row] * HID;
        float4 mv = *(const float4*)(d_maggr + (size_t)n * HID + c4);
        sZ[(c4 + 0) * LDR + row] = mv.x * inv + gm[c4 + 0];
        sZ[(c4 + 1) * LDR + row] = mv.y * inv + gm[c4 + 1];
        sZ[(c4 + 2) * LDR + row] = mv.z * inv + gm[c4 + 2];
        sZ[(c4 + 3) * LDR + row] = mv.w * inv + gm[c4 + 3];
    }

    float acc[8][8];
#pragma unroll
    for (int i = 0; i < 8; i++)
#pragma unroll
        for (int j = 0; j < 8; j++) acc[i][j] = 0.f;

    for (int kt = 0; kt < 256; kt += 8) {
        __syncthreads();
        const float* A;
        if (kt < 128) {
            int row = tid >> 1, kqv = (tid & 1) << 2;
            float4 v = *(const float4*)(h + (size_t)sN[row] * HD + kt + kqv);
            sAs[(kqv + 0) * LDR + row] = v.x;
            sAs[(kqv + 1) * LDR + row] = v.y;
            sAs[(kqv + 2) * LDR + row] = v.z;
            sAs[(kqv + 3) * LDR + row] = v.w;
            A = sAs;
        } else {
            A = sZ + (kt - 128) * LDR;
        }
        {
            int k = tid >> 5, c = (tid & 31) << 2;
            *(float4*)(sBs + k * 128 + c) = *(const float4*)(Wh1 + (size_t)(kt + k) * HID + c);
        }
        __syncthreads();
#pragma unroll
        for (int k = 0; k < 8; k++) {
            float4 a0 = *(const float4*)(A + k * LDR + ty * 8);
            float4 a1 = *(const float4*)(A + k * LDR + ty * 8 + 4);
            float4 b0 = *(const float4*)(sBs + k * 128 + tx * 8);
            float4 b1 = *(const float4*)(sBs + k * 128 + tx * 8 + 4);
            float a[8] = {a0.x, a0.y, a0.z, a0.w, a1.x, a1.y, a1.z, a1.w};
            float b[8] = {b0.x, b0.y, b0.z, b0.w, b1.x, b1.y, b1.z, b1.w};
#pragma unroll
            for (int i = 0; i < 8; i++)
#pragma unroll
                for (int j = 0; j < 8; j++) acc[i][j] += a[i] * b[j];
        }
    }
#pragma unroll
    for (int j = 0; j < 8; j++) {
        float bj = bh1[tx * 8 + j];
#pragma unroll
        for (int i = 0; i < 8; i++)
            sX1[(tx * 8 + j) * LDR + ty * 8 + i] = fmaxf(acc[i][j] + bj, 0.f);
    }
    __syncthreads();

    float a2[8][8];
#pragma unroll
    for (int i = 0; i < 8; i++)
#pragma unroll
        for (int j = 0; j < 8; j++) a2[i][j] = 0.f;

    for (int kt = 0; kt < 128; kt += 8) {
        __syncthreads();
        {
            int k = tid >> 5, c = (tid & 31) << 2;
            *(float4*)(sBs + k * 128 + c) = *(const float4*)(Wh2 + (size_t)(kt + k) * HID + c);
        }
        __syncthreads();
#pragma unroll
        for (int k = 0; k < 8; k++) {
            const float* A = sX1 + (kt + k) * LDR;
            float4 a0 = *(const float4*)(A + ty * 8);
            float4 a1 = *(const float4*)(A + ty * 8 + 4);
            float4 b0 = *(const float4*)(sBs + k * 128 + tx * 8);
            float4 b1 = *(const float4*)(sBs + k * 128 + tx * 8 + 4);
            float a[8] = {a0.x, a0.y, a0.z, a0.w, a1.x, a1.y, a1.z, a1.w};
            float b[8] = {b0.x, b0.y, b0.z, b0.w, b1.x, b1.y, b1.z, b1.w};
#pragma unroll
            for (int i = 0; i < 8; i++)
#pragma unroll
                for (int j = 0; j < 8; j++) a2[i][j] += a[i] * b[j];
        }
    }
#pragma unroll
    for (int i = 0; i < 8; i++) {
        int row = ty * 8 + i;
        int n = n0 + row;
        if (n < NND) {
            float o[8];
#pragma unroll
            for (int j = 0; j < 8; j++) {
                float hv = h[(size_t)n * HD + tx * 8 + j];
                o[j] = fmaxf(hv + a2[i][j] + bh2[tx * 8 + j], 0.f);
            }
            *(float4*)(hout + (size_t)n * HD + tx * 8)     = make_float4(o[0], o[1], o[2], o[3]);
            *(float4*)(hout + (size_t)n * HD + tx * 8 + 4) = make_float4(o[4], o[5], o[6], o[7]);
        }
    }
}

// ---------------- graph update ----------------
__global__ void k_graph(const float* __restrict__ g,
                        const float* __restrict__ Wg1, const float* __restrict__ bg1,
                        const float* __restrict__ Wg2, const float* __restrict__ bg2,
                        float* __restrict__ gout) {
    int r = blockIdx.x, c = threadIdx.x;
    __shared__ float sin_[256];
    __shared__ float t_[64];
    float invh = 1.f / (d_gsumh[r] + 1e-16f);
    float inve = 1.f / (d_gsume[r] + 1e-16f);
    sin_[c] = g[r * GD + c];
    for (int i = c; i < HD; i += 64) sin_[GD + i] = d_haggr[r * HD + i] * invh;
    sin_[GD + HD + c] = d_eaggr[r * ED + c] * inve;
    __syncthreads();
    float s = bg1[c];
#pragma unroll 8
    for (int k = 0; k < 256; k++) s += sin_[k] * Wg1[k * GD + c];
    t_[c] = fmaxf(s, 0.f);
    __syncthreads();
    float u = bg2[c];
#pragma unroll
    for (int k = 0; k < 64; k++) u += t_[k] * Wg2[k * GD + c];
    gout[r * GD + c] = fmaxf(g[r * GD + c] + u, 0.f);
}

// ---------------- launcher ----------------
extern "C" void kernel_launch(void* const* d_in, const int* in_sizes, int n_in,
                              void* d_out, int out_size)
{
    const float* h    = (const float*)d_in[0];
    const float* e    = (const float*)d_in[1];
    const float* g    = (const float*)d_in[2];
    const int*   eidx = (const int*)d_in[3];
    const int*   batch= (const int*)d_in[4];
    const float* Wmap = (const float*)d_in[5];  const float* bmap = (const float*)d_in[6];
    const float* Wm1  = (const float*)d_in[7];  const float* bm1  = (const float*)d_in[8];
    const float* Wm2  = (const float*)d_in[9];  const float* bm2  = (const float*)d_in[10];
    const float* Wma  = (const float*)d_in[11]; const float* bma  = (const float*)d_in[12];
    const float* Wh1  = (const float*)d_in[13]; const float* bh1  = (const float*)d_in[14];
    const float* Wh2  = (const float*)d_in[15]; const float* bh2  = (const float*)d_in[16];
    const float* Wha  = (const float*)d_in[17]; const float* bha  = (const float*)d_in[18];
    const float* We1  = (const float*)d_in[19]; const float* be1  = (const float*)d_in[20];
    const float* We2  = (const float*)d_in[21]; const float* be2  = (const float*)d_in[22];
    const float* Wea  = (const float*)d_in[23]; const float* bea  = (const float*)d_in[24];
    const float* Wg1  = (const float*)d_in[25]; const float* bg1  = (const float*)d_in[26];
    const float* Wg2  = (const float*)d_in[27]; const float* bg2  = (const float*)d_in[28];

    float* out   = (float*)d_out;
    float* out_h = out;
    float* out_e = out + (size_t)NND * HD;
    float* out_g = out + (size_t)NND * HD + (size_t)NE * ED;

    const int SMEM_EDGE =
        (128 * PE + 128 * PX + 2 * 128 * PA + 2 * 32 * PB +
         128 + 64 + 128 + 128 + 128 + 128 + 64 + 64 + 3 * 128) * 4;
    const int SMEM_NODE = (128 * LDR + 128 * LDR + 8 * LDR + 8 * 128 + 128) * 4 + 2 * 128 * 4;

    cudaFuncSetAttribute(k_edge, cudaFuncAttributeMaxDynamicSharedMemorySize, SMEM_EDGE);
    cudaFuncSetAttribute(k_node, cudaFuncAttributeMaxDynamicSharedMemorySize, SMEM_NODE);

    k_init<<<512, 256>>>();
    k_gmap<<<NG, 128>>>(g, Wmap, bmap);
    k_hagg<<<(NND * 32 + 255) / 256, 256>>>(h, batch, Wha, bha);
    k_edge<<<NE / 128, 256, SMEM_EDGE>>>(h, e, eidx, batch,
                                         Wm1, bm1, Wm2, bm2, Wma, bma,
                                         We1, be1, We2, be2, Wea, bea, out_e);
    k_node<<<(NND + 127) / 128, 256, SMEM_NODE>>>(h, batch, Wh1, bh1, Wh2, bh2, out_h);
    k_graph<<<NG, 64>>>(g, Wg1, bg1, Wg2, bg2, out_g);
}

// round 6
// speedup vs baseline: 1.1068x; 1.1068x over previous
#include <cuda_runtime.h>

#define NND 20000
#define NE  640000
#define NG  256
#define HD  128
#define ED  64
#define GD  64
#define HID 128

#define PE  68
#define PX  132
#define PU  68
#define PA  36
#define PB  136
#define PB3 72
#define LDR 132

// ---------------- scratch ----------------
__device__ float d_gmap[NG * HID];
__device__ float d_nsum[NND];
__device__ float d_maggr[(size_t)NND * HID];
__device__ float d_gsumh[NG];
__device__ float d_gsume[NG];
__device__ float d_haggr[NG * HID];
__device__ float d_eaggr[NG * ED];

// ---------------- helpers ----------------
__device__ __forceinline__ void mma8(float* c, const unsigned* a, const unsigned* b) {
    asm volatile(
        "mma.sync.aligned.m16n8k8.row.col.f32.tf32.tf32.f32 "
        "{%0,%1,%2,%3}, {%4,%5,%6,%7}, {%8,%9}, {%0,%1,%2,%3};"
        : "+f"(c[0]), "+f"(c[1]), "+f"(c[2]), "+f"(c[3])
        : "r"(a[0]), "r"(a[1]), "r"(a[2]), "r"(a[3]), "r"(b[0]), "r"(b[1]));
}
__device__ __forceinline__ void cp16(void* s, const void* g) {
    unsigned sa = (unsigned)__cvta_generic_to_shared(s);
    asm volatile("cp.async.cg.shared.global [%0], [%1], 16;" :: "r"(sa), "l"(g));
}
#define CP_COMMIT asm volatile("cp.async.commit_group;")
#define CP_WAIT0  asm volatile("cp.async.wait_group 0;")
#define CP_WAIT1  asm volatile("cp.async.wait_group 1;")

__device__ __forceinline__ void red4(float* g, float4 v) {
    asm volatile("red.global.add.v4.f32 [%0], {%1,%2,%3,%4};"
                 :: "l"(g), "f"(v.x), "f"(v.y), "f"(v.z), "f"(v.w) : "memory");
}

// warp-tile GEMM step over one 32-wide k-tile. mt=2 fixed, NT n-tiles of 8 cols.
template <int NT>
__device__ __forceinline__ void gemm_tile(float (*c)[NT][4],
                                          const float* __restrict__ At, int padA, int coff,
                                          const float* __restrict__ Bt, int padB,
                                          int rbase, int cbase, int g, int kq) {
#pragma unroll
    for (int k8 = 0; k8 < 4; k8++) {
        unsigned a[2][4];
#pragma unroll
        for (int mt = 0; mt < 2; mt++) {
            const float* p = At + (rbase + mt * 16 + g) * padA + coff + k8 * 8 + kq;
            a[mt][0] = __float_as_uint(p[0]);
            a[mt][1] = __float_as_uint(p[8 * padA]);
            a[mt][2] = __float_as_uint(p[4]);
            a[mt][3] = __float_as_uint(p[8 * padA + 4]);
        }
        unsigned b[NT][2];
#pragma unroll
        for (int nt = 0; nt < NT; nt++) {
            const float* p = Bt + (k8 * 8 + kq) * padB + cbase + nt * 8 + g;
            b[nt][0] = __float_as_uint(p[0]);
            b[nt][1] = __float_as_uint(p[4 * padB]);
        }
#pragma unroll
        for (int mt = 0; mt < 2; mt++)
#pragma unroll
            for (int nt = 0; nt < NT; nt++) mma8(c[mt][nt], a[mt], b[nt]);
    }
}

// ---------------- init ----------------
__global__ void k_init() {
    int i  = blockIdx.x * blockDim.x + threadIdx.x;
    int st = gridDim.x * blockDim.x;
    for (int j = i; j < NND; j += st) d_nsum[j] = 0.f;
    for (int j = i; j < NND * HID; j += st) d_maggr[j] = 0.f;
    for (int j = i; j < NG; j += st) { d_gsumh[j] = 0.f; d_gsume[j] = 0.f; }
    for (int j = i; j < NG * HID; j += st) d_haggr[j] = 0.f;
    for (int j = i; j < NG * ED;  j += st) d_eaggr[j] = 0.f;
}

// ---------------- g_map ----------------
__global__ void k_gmap(const float* __restrict__ g, const float* __restrict__ Wmap,
                       const float* __restrict__ bmap) {
    int r = blockIdx.x, c = threadIdx.x;
    __shared__ float sg[GD];
    if (c < GD) sg[c] = g[r * GD + c];
    __syncthreads();
    float s = bmap[c];
#pragma unroll
    for (int k = 0; k < GD; k++) s += sg[k] * Wmap[k * HID + c];
    d_gmap[r * HID + c] = s;
}

// ---------------- node->graph ----------------
__global__ void k_hagg(const float* __restrict__ h, const int* __restrict__ batch,
                       const float* __restrict__ Wha, const float* __restrict__ bhaP) {
    int w = (blockIdx.x * blockDim.x + threadIdx.x) >> 5;
    int lane = threadIdx.x & 31;
    if (w >= NND) return;
    float4 hv = *(const float4*)(h + (size_t)w * HD + lane * 4);
    float4 wv = *(const float4*)(Wha + lane * 4);
    float s = hv.x * wv.x + hv.y * wv.y + hv.z * wv.z + hv.w * wv.w;
#pragma unroll
    for (int off = 16; off; off >>= 1) s += __shfl_xor_sync(0xffffffffu, s, off);
    int b = batch[w];
    float ew = expf(s + bhaP[0]);
    if (lane == 0) atomicAdd(&d_gsumh[b], ew);
    red4(d_haggr + b * HD + lane * 4,
         make_float4(hv.x * ew, hv.y * ew, hv.z * ew, hv.w * ew));
}

// ---------------- fused edge kernel (tf32, 256 thr, 3-stage GEMM1 pipe) -------
__global__ __launch_bounds__(256, 1) void k_edge(
    const float* __restrict__ h, const float* __restrict__ e,
    const int* __restrict__ eidx, const int* __restrict__ batch,
    const float* __restrict__ Wm1, const float* __restrict__ bm1,
    const float* __restrict__ Wm2, const float* __restrict__ bm2,
    const float* __restrict__ Wma, const float* __restrict__ bmaP,
    const float* __restrict__ We1, const float* __restrict__ be1,
    const float* __restrict__ We2, const float* __restrict__ be2,
    const float* __restrict__ Wea, const float* __restrict__ beaP,
    float* __restrict__ eout)
{
    extern __shared__ float smp[];
    float* sE    = smp;                       // 128*PE
    float* sX    = sE + 128 * PE;             // 128*PX
    float* sA    = sX + 128 * PX;             // 3*128*PA (GEMM1 h tiles)
    float* sU    = sA;                        // alias: sA dead after GEMM1
    float* sB    = sA + 3 * 128 * PA;         // 3*32*PB
    float* sWma  = sB + 3 * 32 * PB;          // 128
    float* sWea  = sWma + 128;                // 64
    float* sMatt = sWea + 64;                 // 128
    float* sWeat = sMatt + 128;               // 128
    float* sBm1  = sWeat + 128;               // 128
    float* sBm2  = sBm1 + 128;                // 128
    float* sBe1  = sBm2 + 128;                // 64
    float* sBe2  = sBe1 + 64;                 // 64
    int* sDst = (int*)(sBe2 + 64);
    int* sSrc = sDst + 128;
    int* sBat = sSrc + 128;

    const int tid  = threadIdx.x;
    const int lane = tid & 31;
    const int wid  = tid >> 5;
    const int wy   = wid >> 1;        // 0..3 : rows [wy*32, wy*32+32)
    const int wx   = wid & 1;         // 0..1
    const int g    = lane >> 2;
    const int kq   = lane & 3;
    const int e0   = blockIdx.x * 128;

    // ---- prologue ----
    if (tid < 128) {
        int d = eidx[NE + e0 + tid];
        sDst[tid] = d;
        sSrc[tid] = eidx[e0 + tid];
        sBat[tid] = batch[d];
        sWma[tid] = Wma[tid];
        sMatt[tid] = bmaP[0];
        sBm1[tid] = bm1[tid];
        sBm2[tid] = bm2[tid];
    }
    if (tid < 64) { sWea[tid] = Wea[tid]; sBe1[tid] = be1[tid]; sBe2[tid] = be2[tid]; }
    __syncthreads();

    // ---- async stage: group0 = {sE, A0, B0}; group1 = {A1, B1} ----
#pragma unroll
    for (int i = 0; i < 8; i++) {
        int c = tid + i * 256;
        int row = c >> 4, q = c & 15;
        cp16(sE + row * PE + q * 4, e + (size_t)(e0 + row) * ED + q * 4);
    }
#pragma unroll
    for (int i = 0; i < 4; i++) {
        int c = tid + i * 256;
        int row = c >> 3, q = c & 7;
        cp16(sA + row * PA + q * 4, h + (size_t)sDst[row] * HD + q * 4);
    }
#pragma unroll
    for (int i = 0; i < 4; i++) {
        int c = tid + i * 256;
        int row = c >> 5, q = c & 31;
        cp16(sB + row * PB + q * 4, Wm1 + (size_t)row * HID + q * 4);
    }
    CP_COMMIT;
#pragma unroll
    for (int i = 0; i < 4; i++) {
        int c = tid + i * 256;
        int row = c >> 3, q = c & 7;
        cp16(sA + 128 * PA + row * PA + q * 4, h + (size_t)sDst[row] * HD + 32 + q * 4);
    }
#pragma unroll
    for (int i = 0; i < 4; i++) {
        int c = tid + i * 256;
        int row = c >> 5, q = c & 31;
        cp16(sB + 32 * PB + row * PB + q * 4, Wm1 + (size_t)(32 + row) * HID + q * 4);
    }
    CP_COMMIT;

    // ================= GEMM1: [128,320] @ Wm1 -> X (3-stage pipeline) =========
    float acc[2][8][4];
#pragma unroll
    for (int mt = 0; mt < 2; mt++)
#pragma unroll
        for (int nt = 0; nt < 8; nt++)
#pragma unroll
            for (int i = 0; i < 4; i++) acc[mt][nt][i] = 0.f;

    for (int t = 0; t < 10; t++) {
        if (t < 9) { CP_WAIT1; } else { CP_WAIT0; }
        __syncthreads();
        int tn = t + 2;
        if (tn <= 9) {
            int buf = tn - (tn / 3) * 3;     // tn % 3
            if (tn < 8) {
#pragma unroll
                for (int i = 0; i < 4; i++) {
                    int c = tid + i * 256;
                    int row = c >> 3, q = c & 7;
                    const float* src = (tn < 4)
                        ? h + (size_t)sDst[row] * HD + tn * 32 + q * 4
                        : h + (size_t)sSrc[row] * HD + (tn - 4) * 32 + q * 4;
                    cp16(sA + buf * 128 * PA + row * PA + q * 4, src);
                }
            }
#pragma unroll
            for (int i = 0; i < 4; i++) {
                int c = tid + i * 256;
                int row = c >> 5, q = c & 31;
                cp16(sB + buf * 32 * PB + row * PB + q * 4,
                     Wm1 + (size_t)(tn * 32 + row) * HID + q * 4);
            }
            CP_COMMIT;
        }
        int cbuf = t - (t / 3) * 3;          // t % 3
        const float* At; int padA, coff;
        if (t < 8) { At = sA + cbuf * 128 * PA; padA = PA; coff = 0; }
        else       { At = sE; padA = PE; coff = (t - 8) * 32; }
        gemm_tile<8>(acc, At, padA, coff, sB + cbuf * 32 * PB, PB, wy * 32, wx * 64, g, kq);
    }

    // epilogue 1: X = relu(acc + bm1) -> sX
#pragma unroll
    for (int mt = 0; mt < 2; mt++) {
        int r0 = wy * 32 + mt * 16 + g;
#pragma unroll
        for (int nt = 0; nt < 8; nt++) {
            int col = wx * 64 + nt * 8 + kq * 2;
            float b0 = sBm1[col], b1 = sBm1[col + 1];
            *(float2*)&sX[r0 * PX + col] =
                make_float2(fmaxf(acc[mt][nt][0] + b0, 0.f), fmaxf(acc[mt][nt][1] + b1, 0.f));
            *(float2*)&sX[(r0 + 8) * PX + col] =
                make_float2(fmaxf(acc[mt][nt][2] + b0, 0.f), fmaxf(acc[mt][nt][3] + b1, 0.f));
        }
    }
    __syncthreads();

    // stage GEMM2 B tile0 (buffers 0/1 within sB region)
#pragma unroll
    for (int i = 0; i < 4; i++) {
        int c = tid + i * 256;
        int row = c >> 5, q = c & 31;
        cp16(sB + row * PB + q * 4, Wm2 + (size_t)row * HID + q * 4);
    }
    CP_COMMIT;

    // ================= GEMM2: X @ Wm2 -> m =================
#pragma unroll
    for (int mt = 0; mt < 2; mt++)
#pragma unroll
        for (int nt = 0; nt < 8; nt++)
#pragma unroll
            for (int i = 0; i < 4; i++) acc[mt][nt][i] = 0.f;

    for (int t = 0; t < 4; t++) {
        CP_WAIT0;
        __syncthreads();
        if (t < 3) {
            int tn = t + 1;
#pragma unroll
            for (int i = 0; i < 4; i++) {
                int c = tid + i * 256;
                int row = c >> 5, q = c & 31;
                cp16(sB + ((tn & 1) * 32 * PB) + row * PB + q * 4,
                     Wm2 + (size_t)(tn * 32 + row) * HID + q * 4);
            }
            CP_COMMIT;
        }
        gemm_tile<8>(acc, sX, PX, t * 32, sB + (t & 1) * 32 * PB, PB, wy * 32, wx * 64, g, kq);
    }
    __syncthreads();   // all reads of X done before overwrite with m

    // epilogue 2: m = relu(acc+bm2) -> sX ; m_att partials
    {
        float pa[4] = {0.f, 0.f, 0.f, 0.f};
#pragma unroll
        for (int mt = 0; mt < 2; mt++) {
            int r0 = wy * 32 + mt * 16 + g;
#pragma unroll
            for (int nt = 0; nt < 8; nt++) {
                int col = wx * 64 + nt * 8 + kq * 2;
                float b0 = sBm2[col], b1 = sBm2[col + 1];
                float v0 = fmaxf(acc[mt][nt][0] + b0, 0.f);
                float v1 = fmaxf(acc[mt][nt][1] + b1, 0.f);
                float v2 = fmaxf(acc[mt][nt][2] + b0, 0.f);
                float v3 = fmaxf(acc[mt][nt][3] + b1, 0.f);
                *(float2*)&sX[r0 * PX + col]       = make_float2(v0, v1);
                *(float2*)&sX[(r0 + 8) * PX + col] = make_float2(v2, v3);
                float w0 = sWma[col], w1 = sWma[col + 1];
                pa[mt * 2 + 0] += v0 * w0 + v1 * w1;
                pa[mt * 2 + 1] += v2 * w0 + v3 * w1;
            }
        }
#pragma unroll
        for (int off = 1; off <= 2; off <<= 1)
#pragma unroll
            for (int i = 0; i < 4; i++) pa[i] += __shfl_xor_sync(0xffffffffu, pa[i], off);
        if (kq == 0) {
            atomicAdd(&sMatt[wy * 32 + g],      pa[0]);
            atomicAdd(&sMatt[wy * 32 + g + 8],  pa[1]);
            atomicAdd(&sMatt[wy * 32 + g + 16], pa[2]);
            atomicAdd(&sMatt[wy * 32 + g + 24], pa[3]);
        }
    }
    __syncthreads();

    // per-row softmax weights + edge-att weights
    if (tid < 128) {
        float w = expf(sMatt[tid]);
        sMatt[tid] = w;
        atomicAdd(&d_nsum[sDst[tid]], w);
        float s = beaP[0];
        const float* ep = sE + tid * PE;
#pragma unroll 8
        for (int k = 0; k < ED; k++) s += ep[k] * sWea[k];
        float we = expf(s);
        sWeat[tid] = we;
        atomicAdd(&d_gsume[sBat[tid]], we);
    }
    // stage GEMM3 B tile0 (We1)
#pragma unroll
    for (int i = 0; i < 2; i++) {
        int c = tid + i * 256;
        int row = c >> 4, q = c & 15;
        cp16(sB + row * PB3 + q * 4, We1 + (size_t)row * ED + q * 4);
    }
    CP_COMMIT;
    __syncthreads();

    // combined pass: weighted v4-REDs (maggr, eaggr) + Y = m + gmap in place
    {
        int row = tid >> 1, half = tid & 1;
        float wgt = sMatt[row];
        float wee = sWeat[row];
        int dnode = sDst[row];
        int b = sBat[row];
        const float* gm = d_gmap + (size_t)b * HID + half * 64;
        float* mrow = sX + row * PX + half * 64;
        float* mg = d_maggr + (size_t)dnode * HID + half * 64;
#pragma unroll
        for (int j = 0; j < 16; j++) {
            float4 mv = *(const float4*)(mrow + j * 4);
            red4(mg + j * 4, make_float4(mv.x * wgt, mv.y * wgt, mv.z * wgt, mv.w * wgt));
            float4 gv = *(const float4*)(gm + j * 4);
            *(float4*)(mrow + j * 4) =
                make_float4(mv.x + gv.x, mv.y + gv.y, mv.z + gv.z, mv.w + gv.w);
        }
        const float* ep2 = sE + row * PE + half * 32;
        float* ea = d_eaggr + (size_t)b * ED + half * 32;
#pragma unroll
        for (int j = 0; j < 8; j++) {
            float4 ev = *(const float4*)(ep2 + j * 4);
            red4(ea + j * 4, make_float4(ev.x * wee, ev.y * wee, ev.z * wee, ev.w * wee));
        }
    }

    // ================= GEMM3: [e | Y] (192) @ We1 -> U =================
    float a3[2][4][4];
#pragma unroll
    for (int mt = 0; mt < 2; mt++)
#pragma unroll
        for (int nt = 0; nt < 4; nt++)
#pragma unroll
            for (int i = 0; i < 4; i++) a3[mt][nt][i] = 0.f;

    for (int t = 0; t < 6; t++) {
        CP_WAIT0;
        __syncthreads();
        if (t < 5) {
            int tn = t + 1;
#pragma unroll
            for (int i = 0; i < 2; i++) {
                int c = tid + i * 256;
                int row = c >> 4, q = c & 15;
                cp16(sB + ((tn & 1) * 32 * PB3) + row * PB3 + q * 4,
                     We1 + (size_t)(tn * 32 + row) * ED + q * 4);
            }
            CP_COMMIT;
        }
        const float* At; int padA, coff;
        if (t < 2) { At = sE; padA = PE; coff = t * 32; }
        else       { At = sX; padA = PX; coff = (t - 2) * 32; }
        gemm_tile<4>(a3, At, padA, coff, sB + (t & 1) * 32 * PB3, PB3, wy * 32, wx * 32, g, kq);
    }

    // epilogue 3: U = relu(a3 + be1) -> sU
#pragma unroll
    for (int mt = 0; mt < 2; mt++) {
        int r0 = wy * 32 + mt * 16 + g;
#pragma unroll
        for (int nt = 0; nt < 4; nt++) {
            int col = wx * 32 + nt * 8 + kq * 2;
            float b0 = sBe1[col], b1 = sBe1[col + 1];
            *(float2*)&sU[r0 * PU + col] =
                make_float2(fmaxf(a3[mt][nt][0] + b0, 0.f), fmaxf(a3[mt][nt][1] + b1, 0.f));
            *(float2*)&sU[(r0 + 8) * PU + col] =
                make_float2(fmaxf(a3[mt][nt][2] + b0, 0.f), fmaxf(a3[mt][nt][3] + b1, 0.f));
        }
    }
    // stage GEMM4 B tile0 (We2)
#pragma unroll
    for (int i = 0; i < 2; i++) {
        int c = tid + i * 256;
        int row = c >> 4, q = c & 15;
        cp16(sB + row * PB3 + q * 4, We2 + (size_t)row * ED + q * 4);
    }
    CP_COMMIT;

    // ================= GEMM4: U @ We2 ; e_out = relu(e + . + be2) ============
#pragma unroll
    for (int mt = 0; mt < 2; mt++)
#pragma unroll
        for (int nt = 0; nt < 4; nt++)
#pragma unroll
            for (int i = 0; i < 4; i++) a3[mt][nt][i] = 0.f;

    for (int t = 0; t < 2; t++) {
        CP_WAIT0;
        __syncthreads();
        if (t < 1) {
#pragma unroll
            for (int i = 0; i < 2; i++) {
                int c = tid + i * 256;
                int row = c >> 4, q = c & 15;
                cp16(sB + (32 * PB3) + row * PB3 + q * 4,
                     We2 + (size_t)(32 + row) * ED + q * 4);
            }
            CP_COMMIT;
        }
        gemm_tile<4>(a3, sU, PU, t * 32, sB + (t & 1) * 32 * PB3, PB3, wy * 32, wx * 32, g, kq);
    }

#pragma unroll
    for (int mt = 0; mt < 2; mt++) {
        int r0 = wy * 32 + mt * 16 + g, r1 = r0 + 8;
#pragma unroll
        for (int nt = 0; nt < 4; nt++) {
            int col = wx * 32 + nt * 8 + kq * 2;
            float b0 = sBe2[col], b1 = sBe2[col + 1];
            float2 e0v = *(const float2*)&sE[r0 * PE + col];
            float2 e1v = *(const float2*)&sE[r1 * PE + col];
            *(float2*)&eout[(size_t)(e0 + r0) * ED + col] =
                make_float2(fmaxf(e0v.x + a3[mt][nt][0] + b0, 0.f),
                            fmaxf(e0v.y + a3[mt][nt][1] + b1, 0.f));
            *(float2*)&eout[(size_t)(e0 + r1) * ED + col] =
                make_float2(fmaxf(e1v.x + a3[mt][nt][2] + b0, 0.f),
                            fmaxf(e1v.y + a3[mt][nt][3] + b1, 0.f));
        }
    }
}

// ---------------- node update GEMM (fp32) ----------------
__global__ __launch_bounds__(256, 1) void k_node(
    const float* __restrict__ h, const int* __restrict__ batch,
    const float* __restrict__ Wh1, const float* __restrict__ bh1,
    const float* __restrict__ Wh2, const float* __restrict__ bh2,
    float* __restrict__ hout)
{
    extern __shared__ float smp[];
    float* sZ   = smp;
    float* sX1  = sZ + 128 * LDR;
    float* sAs  = sX1 + 128 * LDR;
    float* sBs  = sAs + 8 * LDR;
    float* sInv = sBs + 8 * 128;
    int* sN  = (int*)(sInv + 128);
    int* sBt = sN + 128;

    int tid = threadIdx.x, tx = tid & 15, ty = tid >> 4;
    int n0 = blockIdx.x * 128;
    if (tid < 128) {
        int n = n0 + tid;
        if (n >= NND) n = NND - 1;
        sN[tid] = n;
        sBt[tid] = batch[n];
        sInv[tid] = 1.f / (d_nsum[n] + 1e-16f);
    }
    __syncthreads();
    for (int i = tid; i < 128 * 32; i += 256) {
        int row = i >> 5, c4 = (i & 31) << 2;
        int n = sN[row];
        float inv = sInv[row];
        const float* gm = d_gmap + (size_t)sBt[row] * HID;
        float4 mv = *(const float4*)(d_maggr + (size_t)n * HID + c4);
        sZ[(c4 + 0) * LDR + row] = mv.x * inv + gm[c4 + 0];
        sZ[(c4 + 1) * LDR + row] = mv.y * inv + gm[c4 + 1];
        sZ[(c4 + 2) * LDR + row] = mv.z * inv + gm[c4 + 2];
        sZ[(c4 + 3) * LDR + row] = mv.w * inv + gm[c4 + 3];
    }

    float acc[8][8];
#pragma unroll
    for (int i = 0; i < 8; i++)
#pragma unroll
        for (int j = 0; j < 8; j++) acc[i][j] = 0.f;

    for (int kt = 0; kt < 256; kt += 8) {
        __syncthreads();
        const float* A;
        if (kt < 128) {
            int row = tid >> 1, kqv = (tid & 1) << 2;
            float4 v = *(const float4*)(h + (size_t)sN[row] * HD + kt + kqv);
            sAs[(kqv + 0) * LDR + row] = v.x;
            sAs[(kqv + 1) * LDR + row] = v.y;
            sAs[(kqv + 2) * LDR + row] = v.z;
            sAs[(kqv + 3) * LDR + row] = v.w;
            A = sAs;
        } else {
            A = sZ + (kt - 128) * LDR;
        }
        {
            int k = tid >> 5, c = (tid & 31) << 2;
            *(float4*)(sBs + k * 128 + c) = *(const float4*)(Wh1 + (size_t)(kt + k) * HID + c);
        }
        __syncthreads();
#pragma unroll
        for (int k = 0; k < 8; k++) {
            float4 a0 = *(const float4*)(A + k * LDR + ty * 8);
            float4 a1 = *(const float4*)(A + k * LDR + ty * 8 + 4);
            float4 b0 = *(const float4*)(sBs + k * 128 + tx * 8);
            float4 b1 = *(const float4*)(sBs + k * 128 + tx * 8 + 4);
            float a[8] = {a0.x, a0.y, a0.z, a0.w, a1.x, a1.y, a1.z, a1.w};
            float b[8] = {b0.x, b0.y, b0.z, b0.w, b1.x, b1.y, b1.z, b1.w};
#pragma unroll
            for (int i = 0; i < 8; i++)
#pragma unroll
                for (int j = 0; j < 8; j++) acc[i][j] += a[i] * b[j];
        }
    }
#pragma unroll
    for (int j = 0; j < 8; j++) {
        float bj = bh1[tx * 8 + j];
#pragma unroll
        for (int i = 0; i < 8; i++)
            sX1[(tx * 8 + j) * LDR + ty * 8 + i] = fmaxf(acc[i][j] + bj, 0.f);
    }
    __syncthreads();

    float a2[8][8];
#pragma unroll
    for (int i = 0; i < 8; i++)
#pragma unroll
        for (int j = 0; j < 8; j++) a2[i][j] = 0.f;

    for (int kt = 0; kt < 128; kt += 8) {
        __syncthreads();
        {
            int k = tid >> 5, c = (tid & 31) << 2;
            *(float4*)(sBs + k * 128 + c) = *(const float4*)(Wh2 + (size_t)(kt + k) * HID + c);
        }
        __syncthreads();
#pragma unroll
        for (int k = 0; k < 8; k++) {
            const float* A = sX1 + (kt + k) * LDR;
            float4 a0 = *(const float4*)(A + ty * 8);
            float4 a1 = *(const float4*)(A + ty * 8 + 4);
            float4 b0 = *(const float4*)(sBs + k * 128 + tx * 8);
            float4 b1 = *(const float4*)(sBs + k * 128 + tx * 8 + 4);
            float a[8] = {a0.x, a0.y, a0.z, a0.w, a1.x, a1.y, a1.z, a1.w};
            float b[8] = {b0.x, b0.y, b0.z, b0.w, b1.x, b1.y, b1.z, b1.w};
#pragma unroll
            for (int i = 0; i < 8; i++)
#pragma unroll
                for (int j = 0; j < 8; j++) a2[i][j] += a[i] * b[j];
        }
    }
#pragma unroll
    for (int i = 0; i < 8; i++) {
        int row = ty * 8 + i;
        int n = n0 + row;
        if (n < NND) {
            float o[8];
#pragma unroll
            for (int j = 0; j < 8; j++) {
                float hv = h[(size_t)n * HD + tx * 8 + j];
                o[j] = fmaxf(hv + a2[i][j] + bh2[tx * 8 + j], 0.f);
            }
            *(float4*)(hout + (size_t)n * HD + tx * 8)     = make_float4(o[0], o[1], o[2], o[3]);
            *(float4*)(hout + (size_t)n * HD + tx * 8 + 4) = make_float4(o[4], o[5], o[6], o[7]);
        }
    }
}

// ---------------- graph update ----------------
__global__ void k_graph(const float* __restrict__ g,
                        const float* __restrict__ Wg1, const float* __restrict__ bg1,
                        const float* __restrict__ Wg2, const float* __restrict__ bg2,
                        float* __restrict__ gout) {
    int r = blockIdx.x, c = threadIdx.x;
    __shared__ float sin_[256];
    __shared__ float t_[64];
    float invh = 1.f / (d_gsumh[r] + 1e-16f);
    float inve = 1.f / (d_gsume[r] + 1e-16f);
    sin_[c] = g[r * GD + c];
    for (int i = c; i < HD; i += 64) sin_[GD + i] = d_haggr[r * HD + i] * invh;
    sin_[GD + HD + c] = d_eaggr[r * ED + c] * inve;
    __syncthreads();
    float s = bg1[c];
#pragma unroll 8
    for (int k = 0; k < 256; k++) s += sin_[k] * Wg1[k * GD + c];
    t_[c] = fmaxf(s, 0.f);
    __syncthreads();
    float u = bg2[c];
#pragma unroll
    for (int k = 0; k < 64; k++) u += t_[k] * Wg2[k * GD + c];
    gout[r * GD + c] = fmaxf(g[r * GD + c] + u, 0.f);
}

// ---------------- launcher ----------------
extern "C" void kernel_launch(void* const* d_in, const int* in_sizes, int n_in,
                              void* d_out, int out_size)
{
    const float* h    = (const float*)d_in[0];
    const float* e    = (const float*)d_in[1];
    const float* g    = (const float*)d_in[2];
    const int*   eidx = (const int*)d_in[3];
    const int*   batch= (const int*)d_in[4];
    const float* Wmap = (const float*)d_in[5];  const float* bmap = (const float*)d_in[6];
    const float* Wm1  = (const float*)d_in[7];  const float* bm1  = (const float*)d_in[8];
    const float* Wm2  = (const float*)d_in[9];  const float* bm2  = (const float*)d_in[10];
    const float* Wma  = (const float*)d_in[11]; const float* bma  = (const float*)d_in[12];
    const float* Wh1  = (const float*)d_in[13]; const float* bh1  = (const float*)d_in[14];
    const float* Wh2  = (const float*)d_in[15]; const float* bh2  = (const float*)d_in[16];
    const float* Wha  = (const float*)d_in[17]; const float* bha  = (const float*)d_in[18];
    const float* We1  = (const float*)d_in[19]; const float* be1  = (const float*)d_in[20];
    const float* We2  = (const float*)d_in[21]; const float* be2  = (const float*)d_in[22];
    const float* Wea  = (const float*)d_in[23]; const float* bea  = (const float*)d_in[24];
    const float* Wg1  = (const float*)d_in[25]; const float* bg1  = (const float*)d_in[26];
    const float* Wg2  = (const float*)d_in[27]; const float* bg2  = (const float*)d_in[28];

    float* out   = (float*)d_out;
    float* out_h = out;
    float* out_e = out + (size_t)NND * HD;
    float* out_g = out + (size_t)NND * HD + (size_t)NE * ED;

    const int SMEM_EDGE =
        (128 * PE + 128 * PX + 3 * 128 * PA + 3 * 32 * PB +
         128 + 64 + 128 + 128 + 128 + 128 + 64 + 64 + 3 * 128) * 4;
    const int SMEM_NODE = (128 * LDR + 128 * LDR + 8 * LDR + 8 * 128 + 128) * 4 + 2 * 128 * 4;

    cudaFuncSetAttribute(k_edge, cudaFuncAttributeMaxDynamicSharedMemorySize, SMEM_EDGE);
    cudaFuncSetAttribute(k_node, cudaFuncAttributeMaxDynamicSharedMemorySize, SMEM_NODE);

    k_init<<<512, 256>>>();
    k_gmap<<<NG, 128>>>(g, Wmap, bmap);
    k_hagg<<<(NND * 32 + 255) / 256, 256>>>(h, batch, Wha, bha);
    k_edge<<<NE / 128, 256, SMEM_EDGE>>>(h, e, eidx, batch,
                                         Wm1, bm1, Wm2, bm2, Wma, bma,
                                         We1, be1, We2, be2, Wea, bea, out_e);
    k_node<<<(NND + 127) / 128, 256, SMEM_NODE>>>(h, batch, Wh1, bh1, Wh2, bh2, out_h);
    k_graph<<<NG, 64>>>(g, Wg1, bg1, Wg2, bg2, out_g);
}

// round 8
// speedup vs baseline: 1.2314x; 1.1125x over previous
#include <cuda_runtime.h>

#define NND 20000
#define NE  640000
#define NG  256
#define HD  128
#define ED  64
#define GD  64
#define HID 128

#define PE  68
#define PX  132
#define PU  68
#define PA  36
#define PB  136
#define PB3 72

// ---------------- scratch ----------------
__device__ float d_gmap[NG * HID];
__device__ float d_nsum[NND];
__device__ float d_maggr[(size_t)NND * HID];
__device__ float d_gsumh[NG];
__device__ float d_gsume[NG];
__device__ float d_haggr[NG * HID];
__device__ float d_eaggr[NG * ED];

// ---------------- helpers ----------------
__device__ __forceinline__ void mma8(float* c, const unsigned* a, const unsigned* b) {
    asm volatile(
        "mma.sync.aligned.m16n8k8.row.col.f32.tf32.tf32.f32 "
        "{%0,%1,%2,%3}, {%4,%5,%6,%7}, {%8,%9}, {%0,%1,%2,%3};"
        : "+f"(c[0]), "+f"(c[1]), "+f"(c[2]), "+f"(c[3])
        : "r"(a[0]), "r"(a[1]), "r"(a[2]), "r"(a[3]), "r"(b[0]), "r"(b[1]));
}
__device__ __forceinline__ void cp16(void* s, const void* g) {
    unsigned sa = (unsigned)__cvta_generic_to_shared(s);
    asm volatile("cp.async.cg.shared.global [%0], [%1], 16;" :: "r"(sa), "l"(g));
}
#define CP_COMMIT asm volatile("cp.async.commit_group;")
#define CP_WAIT0  asm volatile("cp.async.wait_group 0;")
#define CP_WAIT1  asm volatile("cp.async.wait_group 1;")

__device__ __forceinline__ void red4(float* g, float4 v) {
    asm volatile("red.global.add.v4.f32 [%0], {%1,%2,%3,%4};"
                 :: "l"(g), "f"(v.x), "f"(v.y), "f"(v.z), "f"(v.w) : "memory");
}
// tf32 A fragment (16x8 f32) via one ldmatrix.x4 (b16 view of four 8x4-f32 tiles)
__device__ __forceinline__ void ldsmA(unsigned* a, const float* p) {
    unsigned addr = (unsigned)__cvta_generic_to_shared(p);
    asm volatile("ldmatrix.sync.aligned.m8n8.x4.shared.b16 {%0,%1,%2,%3}, [%4];"
                 : "=r"(a[0]), "=r"(a[1]), "=r"(a[2]), "=r"(a[3]) : "r"(addr));
}

// warp-tile GEMM step over one 32-wide k-tile. mt=2 fixed, NT n-tiles of 8 cols.
// A fragments via ldmatrix; B scalar.
template <int NT>
__device__ __forceinline__ void gemm_tile(float (*c)[NT][4],
                                          const float* __restrict__ At, int padA, int coff,
                                          const float* __restrict__ Bt, int padB,
                                          int rbase, int cbase, int g, int kq) {
    const int lane = (g << 2) | kq;
    const int rsel = lane & 15;            // row within 16-row m-tile
    const int csel = (lane >> 4) << 2;     // 0 or 4 (f32 col offset)
#pragma unroll
    for (int k8 = 0; k8 < 4; k8++) {
        unsigned a[2][4];
#pragma unroll
        for (int mt = 0; mt < 2; mt++) {
            const float* p = At + (rbase + mt * 16 + rsel) * padA + coff + k8 * 8 + csel;
            ldsmA(a[mt], p);
        }
        unsigned b[NT][2];
#pragma unroll
        for (int nt = 0; nt < NT; nt++) {
            const float* p = Bt + (k8 * 8 + kq) * padB + cbase + nt * 8 + g;
            b[nt][0] = __float_as_uint(p[0]);
            b[nt][1] = __float_as_uint(p[4 * padB]);
        }
#pragma unroll
        for (int mt = 0; mt < 2; mt++)
#pragma unroll
            for (int nt = 0; nt < NT; nt++) mma8(c[mt][nt], a[mt], b[nt]);
    }
}

// ---------------- init ----------------
__global__ void k_init() {
    int i  = blockIdx.x * blockDim.x + threadIdx.x;
    int st = gridDim.x * blockDim.x;
    for (int j = i; j < NND; j += st) d_nsum[j] = 0.f;
    for (int j = i; j < NND * HID; j += st) d_maggr[j] = 0.f;
    for (int j = i; j < NG; j += st) { d_gsumh[j] = 0.f; d_gsume[j] = 0.f; }
    for (int j = i; j < NG * HID; j += st) d_haggr[j] = 0.f;
    for (int j = i; j < NG * ED;  j += st) d_eaggr[j] = 0.f;
}

// ---------------- g_map ----------------
__global__ void k_gmap(const float* __restrict__ g, const float* __restrict__ Wmap,
                       const float* __restrict__ bmap) {
    int r = blockIdx.x, c = threadIdx.x;
    __shared__ float sg[GD];
    if (c < GD) sg[c] = g[r * GD + c];
    __syncthreads();
    float s = bmap[c];
#pragma unroll
    for (int k = 0; k < GD; k++) s += sg[k] * Wmap[k * HID + c];
    d_gmap[r * HID + c] = s;
}

// ---------------- node->graph ----------------
__global__ void k_hagg(const float* __restrict__ h, const int* __restrict__ batch,
                       const float* __restrict__ Wha, const float* __restrict__ bhaP) {
    int w = (blockIdx.x * blockDim.x + threadIdx.x) >> 5;
    int lane = threadIdx.x & 31;
    if (w >= NND) return;
    float4 hv = *(const float4*)(h + (size_t)w * HD + lane * 4);
    float4 wv = *(const float4*)(Wha + lane * 4);
    float s = hv.x * wv.x + hv.y * wv.y + hv.z * wv.z + hv.w * wv.w;
#pragma unroll
    for (int off = 16; off; off >>= 1) s += __shfl_xor_sync(0xffffffffu, s, off);
    int b = batch[w];
    float ew = expf(s + bhaP[0]);
    if (lane == 0) atomicAdd(&d_gsumh[b], ew);
    red4(d_haggr + b * HD + lane * 4,
         make_float4(hv.x * ew, hv.y * ew, hv.z * ew, hv.w * ew));
}

// ---------------- fused edge kernel (tf32, 256 thr, 3-stage GEMM1 pipe) -------
__global__ __launch_bounds__(256, 1) void k_edge(
    const float* __restrict__ h, const float* __restrict__ e,
    const int* __restrict__ eidx, const int* __restrict__ batch,
    const float* __restrict__ Wm1, const float* __restrict__ bm1,
    const float* __restrict__ Wm2, const float* __restrict__ bm2,
    const float* __restrict__ Wma, const float* __restrict__ bmaP,
    const float* __restrict__ We1, const float* __restrict__ be1,
    const float* __restrict__ We2, const float* __restrict__ be2,
    const float* __restrict__ Wea, const float* __restrict__ beaP,
    float* __restrict__ eout)
{
    extern __shared__ float smp[];
    float* sE    = smp;                       // 128*PE
    float* sX    = sE + 128 * PE;             // 128*PX
    float* sA    = sX + 128 * PX;             // 3*128*PA
    float* sU    = sA;                        // alias: sA dead after GEMM1
    float* sB    = sA + 3 * 128 * PA;         // 3*32*PB
    float* sWma  = sB + 3 * 32 * PB;
    float* sWea  = sWma + 128;
    float* sMatt = sWea + 64;
    float* sWeat = sMatt + 128;
    float* sBm1  = sWeat + 128;
    float* sBm2  = sBm1 + 128;
    float* sBe1  = sBm2 + 128;
    float* sBe2  = sBe1 + 64;
    int* sDst = (int*)(sBe2 + 64);
    int* sSrc = sDst + 128;
    int* sBat = sSrc + 128;

    const int tid  = threadIdx.x;
    const int lane = tid & 31;
    const int wid  = tid >> 5;
    const int wy   = wid >> 1;
    const int wx   = wid & 1;
    const int g    = lane >> 2;
    const int kq   = lane & 3;
    const int e0   = blockIdx.x * 128;

    if (tid < 128) {
        int d = eidx[NE + e0 + tid];
        sDst[tid] = d;
        sSrc[tid] = eidx[e0 + tid];
        sBat[tid] = batch[d];
        sWma[tid] = Wma[tid];
        sMatt[tid] = bmaP[0];
        sBm1[tid] = bm1[tid];
        sBm2[tid] = bm2[tid];
    }
    if (tid < 64) { sWea[tid] = Wea[tid]; sBe1[tid] = be1[tid]; sBe2[tid] = be2[tid]; }
    __syncthreads();

#pragma unroll
    for (int i = 0; i < 8; i++) {
        int c = tid + i * 256;
        int row = c >> 4, q = c & 15;
        cp16(sE + row * PE + q * 4, e + (size_t)(e0 + row) * ED + q * 4);
    }
#pragma unroll
    for (int i = 0; i < 4; i++) {
        int c = tid + i * 256;
        int row = c >> 3, q = c & 7;
        cp16(sA + row * PA + q * 4, h + (size_t)sDst[row] * HD + q * 4);
    }
#pragma unroll
    for (int i = 0; i < 4; i++) {
        int c = tid + i * 256;
        int row = c >> 5, q = c & 31;
        cp16(sB + row * PB + q * 4, Wm1 + (size_t)row * HID + q * 4);
    }
    CP_COMMIT;
#pragma unroll
    for (int i = 0; i < 4; i++) {
        int c = tid + i * 256;
        int row = c >> 3, q = c & 7;
        cp16(sA + 128 * PA + row * PA + q * 4, h + (size_t)sDst[row] * HD + 32 + q * 4);
    }
#pragma unroll
    for (int i = 0; i < 4; i++) {
        int c = tid + i * 256;
        int row = c >> 5, q = c & 31;
        cp16(sB + 32 * PB + row * PB + q * 4, Wm1 + (size_t)(32 + row) * HID + q * 4);
    }
    CP_COMMIT;

    // ================= GEMM1: [128,320] @ Wm1 -> X (3-stage) =================
    float acc[2][8][4];
#pragma unroll
    for (int mt = 0; mt < 2; mt++)
#pragma unroll
        for (int nt = 0; nt < 8; nt++)
#pragma unroll
            for (int i = 0; i < 4; i++) acc[mt][nt][i] = 0.f;

    for (int t = 0; t < 10; t++) {
        if (t < 9) { CP_WAIT1; } else { CP_WAIT0; }
        __syncthreads();
        int tn = t + 2;
        if (tn <= 9) {
            int buf = tn - (tn / 3) * 3;
            if (tn < 8) {
#pragma unroll
                for (int i = 0; i < 4; i++) {
                    int c = tid + i * 256;
                    int row = c >> 3, q = c & 7;
                    const float* src = (tn < 4)
                        ? h + (size_t)sDst[row] * HD + tn * 32 + q * 4
                        : h + (size_t)sSrc[row] * HD + (tn - 4) * 32 + q * 4;
                    cp16(sA + buf * 128 * PA + row * PA + q * 4, src);
                }
            }
#pragma unroll
            for (int i = 0; i < 4; i++) {
                int c = tid + i * 256;
                int row = c >> 5, q = c & 31;
                cp16(sB + buf * 32 * PB + row * PB + q * 4,
                     Wm1 + (size_t)(tn * 32 + row) * HID + q * 4);
            }
            CP_COMMIT;
        }
        int cbuf = t - (t / 3) * 3;
        const float* At; int padA, coff;
        if (t < 8) { At = sA + cbuf * 128 * PA; padA = PA; coff = 0; }
        else       { At = sE; padA = PE; coff = (t - 8) * 32; }
        gemm_tile<8>(acc, At, padA, coff, sB + cbuf * 32 * PB, PB, wy * 32, wx * 64, g, kq);
    }

    // epilogue 1
#pragma unroll
    for (int mt = 0; mt < 2; mt++) {
        int r0 = wy * 32 + mt * 16 + g;
#pragma unroll
        for (int nt = 0; nt < 8; nt++) {
            int col = wx * 64 + nt * 8 + kq * 2;
            float b0 = sBm1[col], b1 = sBm1[col + 1];
            *(float2*)&sX[r0 * PX + col] =
                make_float2(fmaxf(acc[mt][nt][0] + b0, 0.f), fmaxf(acc[mt][nt][1] + b1, 0.f));
            *(float2*)&sX[(r0 + 8) * PX + col] =
                make_float2(fmaxf(acc[mt][nt][2] + b0, 0.f), fmaxf(acc[mt][nt][3] + b1, 0.f));
        }
    }
    __syncthreads();

#pragma unroll
    for (int i = 0; i < 4; i++) {
        int c = tid + i * 256;
        int row = c >> 5, q = c & 31;
        cp16(sB + row * PB + q * 4, Wm2 + (size_t)row * HID + q * 4);
    }
    CP_COMMIT;

    // ================= GEMM2 =================
#pragma unroll
    for (int mt = 0; mt < 2; mt++)
#pragma unroll
        for (int nt = 0; nt < 8; nt++)
#pragma unroll
            for (int i = 0; i < 4; i++) acc[mt][nt][i] = 0.f;

    for (int t = 0; t < 4; t++) {
        CP_WAIT0;
        __syncthreads();
        if (t < 3) {
            int tn = t + 1;
#pragma unroll
            for (int i = 0; i < 4; i++) {
                int c = tid + i * 256;
                int row = c >> 5, q = c & 31;
                cp16(sB + ((tn & 1) * 32 * PB) + row * PB + q * 4,
                     Wm2 + (size_t)(tn * 32 + row) * HID + q * 4);
            }
            CP_COMMIT;
        }
        gemm_tile<8>(acc, sX, PX, t * 32, sB + (t & 1) * 32 * PB, PB, wy * 32, wx * 64, g, kq);
    }
    __syncthreads();

    // epilogue 2
    {
        float pa[4] = {0.f, 0.f, 0.f, 0.f};
#pragma unroll
        for (int mt = 0; mt < 2; mt++) {
            int r0 = wy * 32 + mt * 16 + g;
#pragma unroll
            for (int nt = 0; nt < 8; nt++) {
                int col = wx * 64 + nt * 8 + kq * 2;
                float b0 = sBm2[col], b1 = sBm2[col + 1];
                float v0 = fmaxf(acc[mt][nt][0] + b0, 0.f);
                float v1 = fmaxf(acc[mt][nt][1] + b1, 0.f);
                float v2 = fmaxf(acc[mt][nt][2] + b0, 0.f);
                float v3 = fmaxf(acc[mt][nt][3] + b1, 0.f);
                *(float2*)&sX[r0 * PX + col]       = make_float2(v0, v1);
                *(float2*)&sX[(r0 + 8) * PX + col] = make_float2(v2, v3);
                float w0 = sWma[col], w1 = sWma[col + 1];
                pa[mt * 2 + 0] += v0 * w0 + v1 * w1;
                pa[mt * 2 + 1] += v2 * w0 + v3 * w1;
            }
        }
#pragma unroll
        for (int off = 1; off <= 2; off <<= 1)
#pragma unroll
            for (int i = 0; i < 4; i++) pa[i] += __shfl_xor_sync(0xffffffffu, pa[i], off);
        if (kq == 0) {
            atomicAdd(&sMatt[wy * 32 + g],      pa[0]);
            atomicAdd(&sMatt[wy * 32 + g + 8],  pa[1]);
            atomicAdd(&sMatt[wy * 32 + g + 16], pa[2]);
            atomicAdd(&sMatt[wy * 32 + g + 24], pa[3]);
        }
    }
    __syncthreads();

    if (tid < 128) {
        float w = expf(sMatt[tid]);
        sMatt[tid] = w;
        atomicAdd(&d_nsum[sDst[tid]], w);
        float s = beaP[0];
        const float* ep = sE + tid * PE;
#pragma unroll 8
        for (int k = 0; k < ED; k++) s += ep[k] * sWea[k];
        float we = expf(s);
        sWeat[tid] = we;
        atomicAdd(&d_gsume[sBat[tid]], we);
    }
#pragma unroll
    for (int i = 0; i < 2; i++) {
        int c = tid + i * 256;
        int row = c >> 4, q = c & 15;
        cp16(sB + row * PB3 + q * 4, We1 + (size_t)row * ED + q * 4);
    }
    CP_COMMIT;
    __syncthreads();

    // weighted v4-REDs + Y = m + gmap in place
    {
        int row = tid >> 1, half = tid & 1;
        float wgt = sMatt[row];
        float wee = sWeat[row];
        int dnode = sDst[row];
        int b = sBat[row];
        const float* gm = d_gmap + (size_t)b * HID + half * 64;
        float* mrow = sX + row * PX + half * 64;
        float* mg = d_maggr + (size_t)dnode * HID + half * 64;
#pragma unroll
        for (int j = 0; j < 16; j++) {
            float4 mv = *(const float4*)(mrow + j * 4);
            red4(mg + j * 4, make_float4(mv.x * wgt, mv.y * wgt, mv.z * wgt, mv.w * wgt));
            float4 gv = *(const float4*)(gm + j * 4);
            *(float4*)(mrow + j * 4) =
                make_float4(mv.x + gv.x, mv.y + gv.y, mv.z + gv.z, mv.w + gv.w);
        }
        const float* ep2 = sE + row * PE + half * 32;
        float* ea = d_eaggr + (size_t)b * ED + half * 32;
#pragma unroll
        for (int j = 0; j < 8; j++) {
            float4 ev = *(const float4*)(ep2 + j * 4);
            red4(ea + j * 4, make_float4(ev.x * wee, ev.y * wee, ev.z * wee, ev.w * wee));
        }
    }

    // ================= GEMM3 =================
    float a3[2][4][4];
#pragma unroll
    for (int mt = 0; mt < 2; mt++)
#pragma unroll
        for (int nt = 0; nt < 4; nt++)
#pragma unroll
            for (int i = 0; i < 4; i++) a3[mt][nt][i] = 0.f;

    for (int t = 0; t < 6; t++) {
        CP_WAIT0;
        __syncthreads();
        if (t < 5) {
            int tn = t + 1;
#pragma unroll
            for (int i = 0; i < 2; i++) {
                int c = tid + i * 256;
                int row = c >> 4, q = c & 15;
                cp16(sB + ((tn & 1) * 32 * PB3) + row * PB3 + q * 4,
                     We1 + (size_t)(tn * 32 + row) * ED + q * 4);
            }
            CP_COMMIT;
        }
        const float* At; int padA, coff;
        if (t < 2) { At = sE; padA = PE; coff = t * 32; }
        else       { At = sX; padA = PX; coff = (t - 2) * 32; }
        gemm_tile<4>(a3, At, padA, coff, sB + (t & 1) * 32 * PB3, PB3, wy * 32, wx * 32, g, kq);
    }

    // epilogue 3
#pragma unroll
    for (int mt = 0; mt < 2; mt++) {
        int r0 = wy * 32 + mt * 16 + g;
#pragma unroll
        for (int nt = 0; nt < 4; nt++) {
            int col = wx * 32 + nt * 8 + kq * 2;
            float b0 = sBe1[col], b1 = sBe1[col + 1];
            *(float2*)&sU[r0 * PU + col] =
                make_float2(fmaxf(a3[mt][nt][0] + b0, 0.f), fmaxf(a3[mt][nt][1] + b1, 0.f));
            *(float2*)&sU[(r0 + 8) * PU + col] =
                make_float2(fmaxf(a3[mt][nt][2] + b0, 0.f), fmaxf(a3[mt][nt][3] + b1, 0.f));
        }
    }
#pragma unroll
    for (int i = 0; i < 2; i++) {
        int c = tid + i * 256;
        int row = c >> 4, q = c & 15;
        cp16(sB + row * PB3 + q * 4, We2 + (size_t)row * ED + q * 4);
    }
    CP_COMMIT;

    // ================= GEMM4 =================
#pragma unroll
    for (int mt = 0; mt < 2; mt++)
#pragma unroll
        for (int nt = 0; nt < 4; nt++)
#pragma unroll
            for (int i = 0; i < 4; i++) a3[mt][nt][i] = 0.f;

    for (int t = 0; t < 2; t++) {
        CP_WAIT0;
        __syncthreads();
        if (t < 1) {
#pragma unroll
            for (int i = 0; i < 2; i++) {
                int c = tid + i * 256;
                int row = c >> 4, q = c & 15;
                cp16(sB + (32 * PB3) + row * PB3 + q * 4,
                     We2 + (size_t)(32 + row) * ED + q * 4);
            }
            CP_COMMIT;
        }
        gemm_tile<4>(a3, sU, PU, t * 32, sB + (t & 1) * 32 * PB3, PB3, wy * 32, wx * 32, g, kq);
    }

#pragma unroll
    for (int mt = 0; mt < 2; mt++) {
        int r0 = wy * 32 + mt * 16 + g, r1 = r0 + 8;
#pragma unroll
        for (int nt = 0; nt < 4; nt++) {
            int col = wx * 32 + nt * 8 + kq * 2;
            float b0 = sBe2[col], b1 = sBe2[col + 1];
            float2 e0v = *(const float2*)&sE[r0 * PE + col];
            float2 e1v = *(const float2*)&sE[r1 * PE + col];
            *(float2*)&eout[(size_t)(e0 + r0) * ED + col] =
                make_float2(fmaxf(e0v.x + a3[mt][nt][0] + b0, 0.f),
                            fmaxf(e0v.y + a3[mt][nt][1] + b1, 0.f));
            *(float2*)&eout[(size_t)(e0 + r1) * ED + col] =
                make_float2(fmaxf(e1v.x + a3[mt][nt][2] + b0, 0.f),
                            fmaxf(e1v.y + a3[mt][nt][3] + b1, 0.f));
        }
    }
}

// ---------------- node update: tf32 tensor-core GEMM ----------------
__global__ __launch_bounds__(256, 1) void k_node(
    const float* __restrict__ h, const int* __restrict__ batch,
    const float* __restrict__ Wh1, const float* __restrict__ bh1,
    const float* __restrict__ Wh2, const float* __restrict__ bh2,
    float* __restrict__ hout)
{
    extern __shared__ float smp[];
    float* sZ  = smp;                  // 128*PX : z rows (k 128..255 of input)
    float* sX1 = sZ + 128 * PX;        // 128*PX : layer-1 output
    float* sA  = sX1 + 128 * PX;       // 2*128*PA : staged h tiles
    float* sB  = sA + 2 * 128 * PA;    // 2*32*PB : weight tiles
    float* sB1 = sB + 2 * 32 * PB;     // bh1 (128)
    float* sB2 = sB1 + 128;            // bh2 (128)
    int*   sN  = (int*)(sB2 + 128);    // node ids (128)

    const int tid  = threadIdx.x;
    const int lane = tid & 31;
    const int wid  = tid >> 5;
    const int wy   = wid >> 1;
    const int wx   = wid & 1;
    const int g    = lane >> 2;
    const int kq   = lane & 3;
    const int n0   = blockIdx.x * 128;

    if (tid < 128) {
        int n = n0 + tid;
        if (n >= NND) n = NND - 1;
        sN[tid] = n;
        sB1[tid] = bh1[tid];
        sB2[tid] = bh2[tid];
    }
    __syncthreads();

    // stage A tile0 (h k0..31) + B tile0 (Wh1 k0..31)
#pragma unroll
    for (int i = 0; i < 4; i++) {
        int c = tid + i * 256;
        int row = c >> 3, q = c & 7;
        cp16(sA + row * PA + q * 4, h + (size_t)sN[row] * HD + q * 4);
    }
#pragma unroll
    for (int i = 0; i < 4; i++) {
        int c = tid + i * 256;
        int row = c >> 5, q = c & 31;
        cp16(sB + row * PB + q * 4, Wh1 + (size_t)row * HID + q * 4);
    }
    CP_COMMIT;

    // build sZ = maggr/nsum + gmap  (rows 128 x 128 cols)
    {
        int row = tid >> 1, halfc = (tid & 1) * 64;
        int n = sN[row];
        float inv = 1.f / (d_nsum[n] + 1e-16f);
        const float* gm = d_gmap + (size_t)batch[n] * HID + halfc;
        const float* mg = d_maggr + (size_t)n * HID + halfc;
        float* zr = sZ + row * PX + halfc;
#pragma unroll
        for (int j = 0; j < 16; j++) {
            float4 mv = *(const float4*)(mg + j * 4);
            float4 gv = *(const float4*)(gm + j * 4);
            *(float4*)(zr + j * 4) =
                make_float4(mv.x * inv + gv.x, mv.y * inv + gv.y,
                            mv.z * inv + gv.z, mv.w * inv + gv.w);
        }
    }

    // ============ GEMM1: [h | z](256) @ Wh1 -> X1 ============
    float acc[2][8][4];
#pragma unroll
    for (int mt = 0; mt < 2; mt++)
#pragma unroll
        for (int nt = 0; nt < 8; nt++)
#pragma unroll
            for (int i = 0; i < 4; i++) acc[mt][nt][i] = 0.f;

    for (int t = 0; t < 8; t++) {
        CP_WAIT0;
        __syncthreads();
        if (t < 7) {
            int tn = t + 1;
            if (tn < 4) {
#pragma unroll
                for (int i = 0; i < 4; i++) {
                    int c = tid + i * 256;
                    int row = c >> 3, q = c & 7;
                    cp16(sA + ((tn & 1) * 128 * PA) + row * PA + q * 4,
                         h + (size_t)sN[row] * HD + tn * 32 + q * 4);
                }
            }
#pragma unroll
            for (int i = 0; i < 4; i++) {
                int c = tid + i * 256;
                int row = c >> 5, q = c & 31;
                cp16(sB + ((tn & 1) * 32 * PB) + row * PB + q * 4,
                     Wh1 + (size_t)(tn * 32 + row) * HID + q * 4);
            }
            CP_COMMIT;
        }
        const float* At; int padA, coff;
        if (t < 4) { At = sA + (t & 1) * 128 * PA; padA = PA; coff = 0; }
        else       { At = sZ; padA = PX; coff = (t - 4) * 32; }
        gemm_tile<8>(acc, At, padA, coff, sB + (t & 1) * 32 * PB, PB, wy * 32, wx * 64, g, kq);
    }

    // epilogue 1: X1 = relu(acc + bh1)
#pragma unroll
    for (int mt = 0; mt < 2; mt++) {
        int r0 = wy * 32 + mt * 16 + g;
#pragma unroll
        for (int nt = 0; nt < 8; nt++) {
            int col = wx * 64 + nt * 8 + kq * 2;
            float b0 = sB1[col], b1 = sB1[col + 1];
            *(float2*)&sX1[r0 * PX + col] =
                make_float2(fmaxf(acc[mt][nt][0] + b0, 0.f), fmaxf(acc[mt][nt][1] + b1, 0.f));
            *(float2*)&sX1[(r0 + 8) * PX + col] =
                make_float2(fmaxf(acc[mt][nt][2] + b0, 0.f), fmaxf(acc[mt][nt][3] + b1, 0.f));
        }
    }
    __syncthreads();

    // stage Wh2 tile0
#pragma unroll
    for (int i = 0; i < 4; i++) {
        int c = tid + i * 256;
        int row = c >> 5, q = c & 31;
        cp16(sB + row * PB + q * 4, Wh2 + (size_t)row * HID + q * 4);
    }
    CP_COMMIT;

    // ============ GEMM2: X1 @ Wh2 ============
#pragma unroll
    for (int mt = 0; mt < 2; mt++)
#pragma unroll
        for (int nt = 0; nt < 8; nt++)
#pragma unroll
            for (int i = 0; i < 4; i++) acc[mt][nt][i] = 0.f;

    for (int t = 0; t < 4; t++) {
        CP_WAIT0;
        __syncthreads();
        if (t < 3) {
            int tn = t + 1;
#pragma unroll
            for (int i = 0; i < 4; i++) {
                int c = tid + i * 256;
                int row = c >> 5, q = c & 31;
                cp16(sB + ((tn & 1) * 32 * PB) + row * PB + q * 4,
                     Wh2 + (size_t)(tn * 32 + row) * HID + q * 4);
            }
            CP_COMMIT;
        }
        gemm_tile<8>(acc, sX1, PX, t * 32, sB + (t & 1) * 32 * PB, PB, wy * 32, wx * 64, g, kq);
    }

    // epilogue 2: hout = relu(h + acc + bh2)
#pragma unroll
    for (int mt = 0; mt < 2; mt++) {
        int r0 = wy * 32 + mt * 16 + g, r1 = r0 + 8;
        int nn0 = n0 + r0, nn1 = n0 + r1;
#pragma unroll
        for (int nt = 0; nt < 8; nt++) {
            int col = wx * 64 + nt * 8 + kq * 2;
            float b0 = sB2[col], b1 = sB2[col + 1];
            if (nn0 < NND) {
                float2 hv = *(const float2*)(h + (size_t)nn0 * HD + col);
                *(float2*)&hout[(size_t)nn0 * HD + col] =
                    make_float2(fmaxf(hv.x + acc[mt][nt][0] + b0, 0.f),
                                fmaxf(hv.y + acc[mt][nt][1] + b1, 0.f));
            }
            if (nn1 < NND) {
                float2 hv = *(const float2*)(h + (size_t)nn1 * HD + col);
                *(float2*)&hout[(size_t)nn1 * HD + col] =
                    make_float2(fmaxf(hv.x + acc[mt][nt][2] + b0, 0.f),
                                fmaxf(hv.y + acc[mt][nt][3] + b1, 0.f));
            }
        }
    }
}

// ---------------- graph update ----------------
__global__ void k_graph(const float* __restrict__ g,
                        const float* __restrict__ Wg1, const float* __restrict__ bg1,
                        const float* __restrict__ Wg2, const float* __restrict__ bg2,
                        float* __restrict__ gout) {
    int r = blockIdx.x, c = threadIdx.x;
    __shared__ float sin_[256];
    __shared__ float t_[64];
    float invh = 1.f / (d_gsumh[r] + 1e-16f);
    float inve = 1.f / (d_gsume[r] + 1e-16f);
    sin_[c] = g[r * GD + c];
    for (int i = c; i < HD; i += 64) sin_[GD + i] = d_haggr[r * HD + i] * invh;
    sin_[GD + HD + c] = d_eaggr[r * ED + c] * inve;
    __syncthreads();
    float s = bg1[c];
#pragma unroll 8
    for (int k = 0; k < 256; k++) s += sin_[k] * Wg1[k * GD + c];
    t_[c] = fmaxf(s, 0.f);
    __syncthreads();
    float u = bg2[c];
#pragma unroll
    for (int k = 0; k < 64; k++) u += t_[k] * Wg2[k * GD + c];
    gout[r * GD + c] = fmaxf(g[r * GD + c] + u, 0.f);
}

// ---------------- launcher ----------------
extern "C" void kernel_launch(void* const* d_in, const int* in_sizes, int n_in,
                              void* d_out, int out_size)
{
    const float* h    = (const float*)d_in[0];
    const float* e    = (const float*)d_in[1];
    const float* g    = (const float*)d_in[2];
    const int*   eidx = (const int*)d_in[3];
    const int*   batch= (const int*)d_in[4];
    const float* Wmap = (const float*)d_in[5];  const float* bmap = (const float*)d_in[6];
    const float* Wm1  = (const float*)d_in[7];  const float* bm1  = (const float*)d_in[8];
    const float* Wm2  = (const float*)d_in[9];  const float* bm2  = (const float*)d_in[10];
    const float* Wma  = (const float*)d_in[11]; const float* bma  = (const float*)d_in[12];
    const float* Wh1  = (const float*)d_in[13]; const float* bh1  = (const float*)d_in[14];
    const float* Wh2  = (const float*)d_in[15]; const float* bh2  = (const float*)d_in[16];
    const float* Wha  = (const float*)d_in[17]; const float* bha  = (const float*)d_in[18];
    const float* We1  = (const float*)d_in[19]; const float* be1  = (const float*)d_in[20];
    const float* We2  = (const float*)d_in[21]; const float* be2  = (const float*)d_in[22];
    const float* Wea  = (const float*)d_in[23]; const float* bea  = (const float*)d_in[24];
    const float* Wg1  = (const float*)d_in[25]; const float* bg1  = (const float*)d_in[26];
    const float* Wg2  = (const float*)d_in[27]; const float* bg2  = (const float*)d_in[28];

    float* out   = (float*)d_out;
    float* out_h = out;
    float* out_e = out + (size_t)NND * HD;
    float* out_g = out + (size_t)NND * HD + (size_t)NE * ED;

    const int SMEM_EDGE =
        (128 * PE + 128 * PX + 3 * 128 * PA + 3 * 32 * PB +
         128 + 64 + 128 + 128 + 128 + 128 + 64 + 64 + 3 * 128) * 4;
    const int SMEM_NODE =
        (2 * 128 * PX + 2 * 128 * PA + 2 * 32 * PB + 128 + 128 + 128) * 4;

    cudaFuncSetAttribute(k_edge, cudaFuncAttributeMaxDynamicSharedMemorySize, SMEM_EDGE);
    cudaFuncSetAttribute(k_node, cudaFuncAttributeMaxDynamicSharedMemorySize, SMEM_NODE);

    k_init<<<512, 256>>>();
    k_gmap<<<NG, 128>>>(g, Wmap, bmap);
    k_hagg<<<(NND * 32 + 255) / 256, 256>>>(h, batch, Wha, bha);
    k_edge<<<NE / 128, 256, SMEM_EDGE>>>(h, e, eidx, batch,
                                         Wm1, bm1, Wm2, bm2, Wma, bma,
                                         We1, be1, We2, be2, Wea, bea, out_e);
    k_node<<<(NND + 127) / 128, 256, SMEM_NODE>>>(h, batch, Wh1, bh1, Wh2, bh2, out_h);
    k_graph<<<NG, 64>>>(g, Wg1, bg1, Wg2, bg2, out_g);
}